// round 7
// baseline (speedup 1.0000x reference)
#include <cuda_runtime.h>
#include <cstdint>

// ---------------- problem dims ----------------
#define CIN   32
#define COUT  32
#define HIN   512
#define WIN   512
#define HOUT  510
#define WOUT  510
#define NB    16

// ---------------- tiling ----------------
#define TY      4              // output rows per CTA (1 per warp)
#define TPX     64             // output px per CTA (n64 per warp)
#define XPX     68             // staged px (64 + 2 halo, padded)
#define THREADS 128

// smem (bytes): 6 input-row slots (tf32) + weights (tf32); rows of 128B
#define XSLOT      (XPX * 128)          // 8704
#define W_OFF      (6 * XSLOT)          // 52224
#define W_BYTES    (288 * 128)          // 36864 (rows: kk*32+co)
#define SMEM_TOTAL (W_OFF + W_BYTES)    // 89088

__device__ __forceinline__ uint32_t smem_u32(const void* p) {
    uint32_t a;
    asm("{ .reg .u64 t; cvta.to.shared.u64 t, %1; cvt.u32.u64 %0, t; }"
        : "=r"(a) : "l"(p));
    return a;
}

__device__ __forceinline__ uint32_t to_tf32(float f) {
    uint32_t u;
    asm("cvt.rna.tf32.f32 %0, %1;" : "=r"(u) : "f"(f));
    return u;
}

#define STS128(addr, a, b, c, d) \
    asm volatile("st.shared.v4.b32 [%0], {%1,%2,%3,%4};" \
        :: "r"(addr), "r"(a), "r"(b), "r"(c), "r"(d) : "memory")

#define LDSM4(r, addr) \
    asm volatile("ldmatrix.sync.aligned.m8n8.x4.shared.b16 {%0,%1,%2,%3}, [%4];" \
        : "=r"((r)[0]), "=r"((r)[1]), "=r"((r)[2]), "=r"((r)[3]) : "r"(addr))

#define MMA_TF32(c, a, b0, b1) \
    asm volatile("mma.sync.aligned.m16n8k8.row.col.f32.tf32.tf32.f32 " \
        "{%0,%1,%2,%3}, {%4,%5,%6,%7}, {%8,%9}, {%0,%1,%2,%3};" \
        : "+f"((c)[0]), "+f"((c)[1]), "+f"((c)[2]), "+f"((c)[3]) \
        : "r"((a)[0]), "r"((a)[1]), "r"((a)[2]), "r"((a)[3]), "r"(b0), "r"(b1))

__global__ __launch_bounds__(THREADS, 2)
void conv_mma_kernel(const float* __restrict__ x,
                     const float* __restrict__ w,
                     const float* __restrict__ bias,
                     float* __restrict__ out)
{
    extern __shared__ char smem[];
    const uint32_t sb = smem_u32(smem);
    const int t    = threadIdx.x;
    const int wid  = t >> 5;        // 0..3 = output row
    const int lane = t & 31;

    const int xt = blockIdx.x;      // 0..7
    const int yt = blockIdx.y;      // 0..127
    const int nb = blockIdx.z;      // 0..15
    const int x0 = xt * TPX;
    const int y0 = yt * TY;

    // ---- stage W (tf32): row = kk*32+co, 128B = 32 ci words, XOR-swizzled
    #pragma unroll 1
    for (int row = t; row < 288; row += THREADS) {
        const int kk = row >> 5;          // ky*3+kx
        const int co = row & 31;
        const float* wp = w + (size_t)co * 288 + kk;   // + ci*9
        const uint32_t rbase = sb + W_OFF + (uint32_t)row * 128;
        const int r7 = row & 7;
        #pragma unroll
        for (int c0 = 0; c0 < CIN; c0 += 4) {
            uint32_t u0 = to_tf32(wp[(size_t)(c0 + 0) * 9]);
            uint32_t u1 = to_tf32(wp[(size_t)(c0 + 1) * 9]);
            uint32_t u2 = to_tf32(wp[(size_t)(c0 + 2) * 9]);
            uint32_t u3 = to_tf32(wp[(size_t)(c0 + 3) * 9]);
            const uint32_t ch = (uint32_t)((c0 >> 2) ^ r7);
            STS128(rbase + (ch << 4), u0, u1, u2, u3);
        }
    }

    // ---- stage X (tf32): 6 input rows x 68 px, 128B px-rows, swizzled
    #pragma unroll 1
    for (int idx = t; idx < 6 * XPX; idx += THREADS) {
        const int s  = idx / XPX;
        const int px = idx - s * XPX;
        const int y_in = y0 + s;
        const int ix   = x0 + px;
        const bool ok = (y_in < HIN) && (ix < WIN);
        const float* xp = x + ((size_t)(nb * CIN) * HIN + y_in) * WIN + ix;
        const uint32_t rbase = sb + (uint32_t)s * XSLOT + (uint32_t)px * 128;
        const int p7 = px & 7;
        #pragma unroll
        for (int c0 = 0; c0 < CIN; c0 += 4) {
            uint32_t u0 = ok ? to_tf32(xp[(size_t)(c0 + 0) * HIN * WIN]) : 0u;
            uint32_t u1 = ok ? to_tf32(xp[(size_t)(c0 + 1) * HIN * WIN]) : 0u;
            uint32_t u2 = ok ? to_tf32(xp[(size_t)(c0 + 2) * HIN * WIN]) : 0u;
            uint32_t u3 = ok ? to_tf32(xp[(size_t)(c0 + 3) * HIN * WIN]) : 0u;
            const uint32_t ch = (uint32_t)((c0 >> 2) ^ p7);
            STS128(rbase + (ch << 4), u0, u1, u2, u3);
        }
    }
    __syncthreads();

    // ---- mainloop: warp = output row wid, m32 co x n64 px, tf32 single pass
    const int r  = wid;
    const int l7 = lane & 7;
    // A ldmatrix lane->row/chunk mapping (m16k8 tile)
    const int a_row = ((lane >> 3) & 1) * 8 + l7;   // row within m16
    const int a_ch  = lane >> 4;                    // 0/1 (ci 4-word chunk)
    // B ldmatrix lane->pxrow/chunk mapping (k8n16 per x4)
    const int b_px = l7 + ((lane >> 4) << 3);       // px within 16
    const int b_ch = (lane >> 3) & 1;

    const int g  = lane >> 2;
    const int tg = lane & 3;

    float c[2][8][4];
    #pragma unroll
    for (int mt = 0; mt < 2; ++mt) {
        const float bv0 = __ldg(bias + mt * 16 + g);
        const float bv1 = __ldg(bias + mt * 16 + 8 + g);
        #pragma unroll
        for (int nt = 0; nt < 8; ++nt) {
            c[mt][nt][0] = bv0; c[mt][nt][1] = bv0;
            c[mt][nt][2] = bv1; c[mt][nt][3] = bv1;
        }
    }

    #pragma unroll
    for (int ky = 0; ky < 3; ++ky) {
        const uint32_t Xs = sb + (uint32_t)(r + ky) * XSLOT;
        #pragma unroll
        for (int kx = 0; kx < 3; ++kx) {
            const int kk = ky * 3 + kx;
            const uint32_t aBase =
                sb + W_OFF + (uint32_t)(kk * 32 + a_row) * 128;
            #pragma unroll
            for (int kc = 0; kc < 4; ++kc) {        // ci 8-chunks
                uint32_t a[2][4];
                #pragma unroll
                for (int mt = 0; mt < 2; ++mt) {
                    const uint32_t ch = (uint32_t)((2 * kc + a_ch) ^ l7);
                    LDSM4(a[mt], aBase + (uint32_t)(mt * 16 * 128) + (ch << 4));
                }
                uint32_t b[4][4];
                #pragma unroll
                for (int q = 0; q < 4; ++q) {       // n16 groups
                    const int prow = 16 * q + kx + b_px;
                    const uint32_t ch = (uint32_t)((2 * kc + b_ch) ^ (prow & 7));
                    LDSM4(b[q], Xs + (uint32_t)prow * 128 + (ch << 4));
                }
                #pragma unroll
                for (int mt = 0; mt < 2; ++mt)
                    #pragma unroll
                    for (int nt = 0; nt < 8; ++nt) {
                        const int q = nt >> 1;
                        const int e = (nt & 1) * 2;
                        MMA_TF32(c[mt][nt], a[mt], b[q][e], b[q][e + 1]);
                    }
            }
        }
    }

    // ---- store (fp32 float2, guarded at edges)
    const int oy = y0 + r;
    if (oy < HOUT) {
        #pragma unroll
        for (int mt = 0; mt < 2; ++mt) {
            const size_t base0 =
                ((size_t)(nb * COUT + mt * 16 + g) * HOUT + oy) * (size_t)WOUT;
            const size_t coStep = (size_t)8 * HOUT * WOUT;
            #pragma unroll
            for (int nt = 0; nt < 8; ++nt) {
                const int ox = x0 + nt * 8 + 2 * tg;
                if (ox < WOUT) {
                    float2 v0 = make_float2(c[mt][nt][0], c[mt][nt][1]);
                    float2 v1 = make_float2(c[mt][nt][2], c[mt][nt][3]);
                    *reinterpret_cast<float2*>(out + base0 + ox)          = v0;
                    *reinterpret_cast<float2*>(out + base0 + coStep + ox) = v1;
                }
            }
        }
    }
}

extern "C" void kernel_launch(void* const* d_in, const int* in_sizes, int n_in,
                              void* d_out, int out_size)
{
    const float* x    = (const float*)d_in[0];
    const float* w    = (const float*)d_in[1];
    const float* bias = (const float*)d_in[2];
    float*       out  = (float*)d_out;

    cudaFuncSetAttribute(conv_mma_kernel,
                         cudaFuncAttributeMaxDynamicSharedMemorySize, SMEM_TOTAL);

    dim3 grid((WOUT + TPX - 1) / TPX,   // 8
              (HOUT + TY - 1) / TY,     // 128
              NB);                      // 16
    conv_mma_kernel<<<grid, THREADS, SMEM_TOTAL>>>(x, w, bias, out);
}

// round 10
// speedup vs baseline: 2.3654x; 2.3654x over previous
#include <cuda_runtime.h>
#include <cuda_fp16.h>
#include <cstdint>

// ---------------- problem dims ----------------
#define CIN   32
#define COUT  32
#define HIN   512
#define WIN   512
#define HOUT  510
#define WOUT  510
#define NB    16

// ---------------- tiling ----------------
#define TY      4              // output rows per CTA
#define TPX     64             // output px per CTA
#define XPX     68             // staged px (64 + 2 halo, padded)
#define THREADS 256

// ---------------- smem layout ----------------
// rows of 80B (64B = 32 ci fp16 + 16B pad): banks (5r+c)%8 distinct -> LDSM conflict-free
#define ROWB       80
#define XSLOT      (XPX * ROWB)         // 5440
#define W_OFF      32768                // X total 6*5440 = 32640
#define W_BYTES    (288 * ROWB)         // 23040 (rows: kk*32+co)
#define SMEM_TOTAL (W_OFF + W_BYTES)    // 55808

// pre-packed weights: [kk*32+co][40 halves] (32 ci + 8 pad)
__device__ __align__(16) __half w_packed[288 * 40];

__device__ __forceinline__ uint32_t smem_u32(const void* p) {
    uint32_t a;
    asm("{ .reg .u64 t; cvta.to.shared.u64 t, %1; cvt.u32.u64 %0, t; }"
        : "=r"(a) : "l"(p));
    return a;
}

__device__ __forceinline__ uint32_t h2u(__half2 h) {
    uint32_t u;
    asm("mov.b32 %0, %1;" : "=r"(u) : "r"(*reinterpret_cast<uint32_t*>(&h)));
    return u;
}

#define STS128(addr, a, b, c, d) \
    asm volatile("st.shared.v4.b32 [%0], {%1,%2,%3,%4};" \
        :: "r"(addr), "r"(a), "r"(b), "r"(c), "r"(d) : "memory")

#define LDSM4(r, addr) \
    asm volatile("ldmatrix.sync.aligned.m8n8.x4.shared.b16 {%0,%1,%2,%3}, [%4];" \
        : "=r"((r)[0]), "=r"((r)[1]), "=r"((r)[2]), "=r"((r)[3]) : "r"(addr))

#define MMA_F16(c, a, b0, b1) \
    asm volatile("mma.sync.aligned.m16n8k16.row.col.f32.f16.f16.f32 " \
        "{%0,%1,%2,%3}, {%4,%5,%6,%7}, {%8,%9}, {%0,%1,%2,%3};" \
        : "+f"((c)[0]), "+f"((c)[1]), "+f"((c)[2]), "+f"((c)[3]) \
        : "r"((a)[0]), "r"((a)[1]), "r"((a)[2]), "r"((a)[3]), "r"(b0), "r"(b1))

// =====================================================================
// setup kernel: w (OIHW fp32) -> w_packed [kk][co][ci] fp16, 80B rows
// =====================================================================
__global__ void pack_w_kernel(const float* __restrict__ w)
{
    int i = blockIdx.x * 256 + threadIdx.x;     // 0..9215
    if (i < 288 * 32) {
        int row = i >> 5;                       // kk*32+co
        int ci  = i & 31;
        int kk  = row >> 5;
        int co  = row & 31;
        w_packed[row * 40 + ci] = __float2half_rn(w[(co * 32 + ci) * 9 + kk]);
    }
}

// =====================================================================
// main kernel: fp16 single-pass implicit-GEMM conv
// =====================================================================
__global__ __launch_bounds__(THREADS, 2)
void conv_mma_kernel(const float* __restrict__ x,
                     const float* __restrict__ bias,
                     float* __restrict__ out)
{
    extern __shared__ char smem[];
    const uint32_t sb = smem_u32(smem);
    const int t    = threadIdx.x;
    const int wid  = t >> 5;
    const int lane = t & 31;

    const int xt = blockIdx.x;       // 0..7
    const int yt = blockIdx.y;       // 0..127
    const int nb = blockIdx.z;       // 0..15
    const int x0 = xt * TPX;
    const int y0 = yt * TY;

    // ---- stage W: straight 16B copy of pre-packed layout
    {
        const uint4* src = reinterpret_cast<const uint4*>(w_packed);
        #pragma unroll 1
        for (int i = t; i < W_BYTES / 16; i += THREADS) {
            uint4 v = src[i];
            STS128(sb + W_OFF + (uint32_t)i * 16, v.x, v.y, v.z, v.w);
        }
    }

    // ---- stage X: per (s, ci-octet): coalesced LDG, STS128 (conflict-free)
    #pragma unroll 1
    for (int pair = wid; pair < 24; pair += 8) {
        const int s = pair >> 2;            // input row 0..5
        const int o = pair & 3;             // ci octet
        const int y_in = y0 + s;
        const bool yok = (y_in < HIN);
        const float* xp =
            x + ((size_t)(nb * CIN + o * 8) * HIN + y_in) * WIN + x0;
        const uint32_t rbase = sb + (uint32_t)s * XSLOT + (uint32_t)o * 16;
        #pragma unroll
        for (int p0 = 0; p0 < XPX; p0 += 32) {
            const int px = p0 + lane;
            if (px < XPX) {
                const bool ok = yok && (x0 + px) < WIN;
                float v[8];
                #pragma unroll
                for (int j = 0; j < 8; ++j)
                    v[j] = ok ? xp[(size_t)j * HIN * WIN + px] : 0.0f;
                __half2 h0 = __floats2half2_rn(v[0], v[1]);
                __half2 h1 = __floats2half2_rn(v[2], v[3]);
                __half2 h2 = __floats2half2_rn(v[4], v[5]);
                __half2 h3 = __floats2half2_rn(v[6], v[7]);
                STS128(rbase + (uint32_t)px * ROWB,
                       h2u(h0), h2u(h1), h2u(h2), h2u(h3));
            }
        }
    }
    __syncthreads();

    // ---- mainloop: warp = (row, px chunk), m32 x n32, fp16 k16 single pass
    const int r   = wid >> 1;          // output row 0..3
    const int pxw = (wid & 1) * 32;    // px chunk base

    const int a_row   = lane & 15;           // A: co row within m16
    const int a_chunk = lane >> 4;           // A: k8 chunk 0/1
    const int b_n     = (lane & 7) | ((lane >> 4) << 3);   // B: px within 16
    const int b_chunk = (lane >> 3) & 1;                   // B: k8 chunk 0/1

    const int g  = lane >> 2;
    const int tg = lane & 3;

    float c[2][4][4];
    #pragma unroll
    for (int mt = 0; mt < 2; ++mt) {
        const float bv0 = __ldg(bias + mt * 16 + g);
        const float bv1 = __ldg(bias + mt * 16 + 8 + g);
        #pragma unroll
        for (int q = 0; q < 4; ++q) {
            c[mt][q][0] = bv0; c[mt][q][1] = bv0;
            c[mt][q][2] = bv1; c[mt][q][3] = bv1;
        }
    }

    #pragma unroll
    for (int ky = 0; ky < 3; ++ky) {
        const uint32_t Xs = sb + (uint32_t)(r + ky) * XSLOT;
        #pragma unroll
        for (int kx = 0; kx < 3; ++kx) {
            const int kk = ky * 3 + kx;
            const uint32_t aBase =
                sb + W_OFF + (uint32_t)(kk * 32 + a_row) * ROWB;
            #pragma unroll
            for (int kc = 0; kc < 2; ++kc) {       // two k16 steps over 32 ci
                const uint32_t aOff = (uint32_t)(2 * kc + a_chunk) * 16;
                const uint32_t bOff = (uint32_t)(2 * kc + b_chunk) * 16;

                uint32_t a[2][4];
                LDSM4(a[0], aBase + aOff);
                LDSM4(a[1], aBase + 16 * ROWB + aOff);

                uint32_t b[2][4];
                #pragma unroll
                for (int g2 = 0; g2 < 2; ++g2) {   // n16 groups
                    const int prow = pxw + kx + g2 * 16 + b_n;
                    LDSM4(b[g2], Xs + (uint32_t)prow * ROWB + bOff);
                }

                #pragma unroll
                for (int mt = 0; mt < 2; ++mt)
                    #pragma unroll
                    for (int q = 0; q < 4; ++q) {
                        const int g2 = q >> 1;
                        const int e  = (q & 1) * 2;
                        MMA_F16(c[mt][q], a[mt], b[g2][e], b[g2][e + 1]);
                    }
            }
        }
    }

    // ---- store (fp32 float2, guarded at edges)
    const int oy = y0 + r;
    if (oy < HOUT) {
        #pragma unroll
        for (int mt = 0; mt < 2; ++mt) {
            const size_t base0 =
                ((size_t)(nb * COUT + mt * 16 + g) * HOUT + oy) * (size_t)WOUT;
            const size_t coStep = (size_t)8 * HOUT * WOUT;
            #pragma unroll
            for (int q = 0; q < 4; ++q) {
                const int ox = x0 + pxw + q * 8 + 2 * tg;
                if (ox < WOUT) {
                    float2 v0 = make_float2(c[mt][q][0], c[mt][q][1]);
                    float2 v1 = make_float2(c[mt][q][2], c[mt][q][3]);
                    *reinterpret_cast<float2*>(out + base0 + ox)          = v0;
                    *reinterpret_cast<float2*>(out + base0 + coStep + ox) = v1;
                }
            }
        }
    }
}

extern "C" void kernel_launch(void* const* d_in, const int* in_sizes, int n_in,
                              void* d_out, int out_size)
{
    const float* x    = (const float*)d_in[0];
    const float* w    = (const float*)d_in[1];
    const float* bias = (const float*)d_in[2];
    float*       out  = (float*)d_out;

    pack_w_kernel<<<36, 256>>>(w);

    cudaFuncSetAttribute(conv_mma_kernel,
                         cudaFuncAttributeMaxDynamicSharedMemorySize, SMEM_TOTAL);

    dim3 grid((WOUT + TPX - 1) / TPX,   // 8
              (HOUT + TY - 1) / TY,     // 128
              NB);                      // 16
    conv_mma_kernel<<<grid, THREADS, SMEM_TOTAL>>>(x, bias, out);
}